// round 5
// baseline (speedup 1.0000x reference)
#include <cuda_runtime.h>

// Problem constants
#define B_  16
#define N_  64
#define S_  4
#define F0_ 8
#define C_  32
#define G_  4          // CTAs per batch (channel slices)
#define XL_ 8          // channels per slice (C_/G_)

// Cross-CTA pool combine scratch
__device__ float    g_part[B_ * G_];
__device__ unsigned g_cnt[B_];        // zero-init; atomicInc wraps -> 0 each call

// Per-CTA shared workspace (~148 KB)
struct Smem {
    float esh[N_][N_][S_];   // staged edge tensor for this batch        (64 KB)
    float wT1[F0_][5][C_];   // layer1 kernel weights transposed [y][s][x]
    float wrs1[F0_][C_];     // layer1 root weights [y][x]
    float U1[N_][5][C_];     // layer1 per-node projections (full)       (40 KB)
    float root1[N_][C_];
    float h1[N_][C_];
    float w2s[C_][32];       // layer2 kernel slice [y][s*8+xl]
    float w2br[C_][16];      // [y][0..7: b2_kern slice, 8..15: w2_root slice]
    float U2[N_][32];        // [i][s*8+xl]
    float U2br[N_][16];      // [i][0..7: bias-kernel slot, 8..15: root2]
    float bs1[C_];
    float bs2s[XL_];
    float maskv[N_];
    float red[32];
};

__global__ __launch_bounds__(1024, 1)
void fused_gnn_kernel(const float* __restrict__ x,
                      const float* __restrict__ a,
                      const float* __restrict__ e,
                      const float* __restrict__ w1k, const float* __restrict__ b1k,
                      const float* __restrict__ w1r, const float* __restrict__ b1,
                      const float* __restrict__ w2k, const float* __restrict__ b2k,
                      const float* __restrict__ w2r, const float* __restrict__ b2,
                      const float* __restrict__ wd,  const float* __restrict__ bd,
                      float* __restrict__ out)
{
    extern __shared__ Smem smem[];
    Smem& s = *smem;

    const int b    = blockIdx.x >> 2;     // batch
    const int g    = blockIdx.x & 3;      // channel slice
    const int tid  = threadIdx.x;
    const int warp = tid >> 5;
    const int lane = tid & 31;

    const float* xb = x + (size_t)b * N_ * (F0_ + 1);
    const float* ab = a + (size_t)b * N_ * N_;
    const float* eb = e + (size_t)b * N_ * N_ * S_;

    // ------------------------------------------------------------------
    // Stage 0a: bulk-stage e for this batch (64 KB) — issued FIRST so the
    // copy latency overlaps the weight staging below. Coalesced float4s.
    // ------------------------------------------------------------------
    {
        const float4* src = (const float4*)eb;
        float4*       dst = (float4*)&s.esh[0][0][0];
        #pragma unroll
        for (int k = 0; k < 4; k++)
            dst[tid + k*1024] = src[tid + k*1024];
    }

    // ------------------------------------------------------------------
    // Stage 0b: weight staging
    // ------------------------------------------------------------------
    for (int i0 = tid; i0 < S_*C_*F0_; i0 += 1024) {
        int sI = i0 / (C_*F0_); int r = i0 - sI*(C_*F0_);
        int xx = r / F0_;       int yy = r - xx*F0_;
        s.wT1[yy][sI][xx] = w1k[i0];
    }
    for (int i0 = tid; i0 < C_*F0_; i0 += 1024) {
        int xx = i0 / F0_, yy = i0 - xx*F0_;
        s.wT1[yy][4][xx] = b1k[i0];
    }
    for (int i0 = tid; i0 < F0_*C_; i0 += 1024)
        (&s.wrs1[0][0])[i0] = w1r[i0];

    // layer2 slice: w2s[y][s*8+xl] = w2k[s*(C*C) + (g*8+xl)*C + y]
    {
        int yy = tid & 31, l = tid >> 5;
        int sI = l >> 3,   xl = l & 7;
        s.w2s[yy][l] = w2k[sI*(C_*C_) + (g*XL_ + xl)*C_ + yy];
    }
    if (tid < 512) {
        int yy = tid & 31, l = tid >> 5;      // l in 0..15
        float v;
        if (l < 8) v = b2k[(g*XL_ + l)*C_ + yy];           // bias-kernel slot
        else       v = w2r[yy*C_ + g*XL_ + (l - 8)];       // root weights
        s.w2br[yy][l] = v;
    }
    if (tid < XL_) s.bs2s[tid] = b2[g*XL_ + tid];
    if (tid < C_)  s.bs1[tid]  = b1[tid];
    __syncthreads();

    // ------------------------------------------------------------------
    // Stage 1: prep1 (full, redundant per slice-CTA). 2 rows/warp, lane=x.
    // ------------------------------------------------------------------
    #pragma unroll
    for (int r = 0; r < 2; r++) {
        const int row = warp*2 + r;
        float xv = (lane <= F0_) ? xb[row*(F0_+1) + lane] : 0.f;
        if (lane == F0_) s.maskv[row] = xv;

        float a0=0.f, a1=0.f, a2=0.f, a3=0.f, a4=0.f;
        float rt = s.bs1[lane];
        #pragma unroll
        for (int y = 0; y < F0_; y++) {
            float hv = __shfl_sync(0xffffffffu, xv, y);
            a0 += s.wT1[y][0][lane] * hv;
            a1 += s.wT1[y][1][lane] * hv;
            a2 += s.wT1[y][2][lane] * hv;
            a3 += s.wT1[y][3][lane] * hv;
            a4 += s.wT1[y][4][lane] * hv;
            rt += s.wrs1[y][lane]   * hv;
        }
        s.U1[row][0][lane] = a0;
        s.U1[row][1][lane] = a1;
        s.U1[row][2][lane] = a2;
        s.U1[row][3][lane] = a3;
        s.U1[row][4][lane] = a4;
        s.root1[row][lane] = rt;
    }

    // Hoist adjacency for both rows (coalesced; reused by msg1 AND msg2)
    const int row0 = warp*2, row1 = row0 + 1;
    const float avA0 = ab[(size_t)row0*N_ + lane];
    const float avA1 = ab[(size_t)row0*N_ + 32 + lane];
    const float avB0 = ab[(size_t)row1*N_ + lane];
    const float avB1 = ab[(size_t)row1*N_ + 32 + lane];
    const unsigned mA0 = __ballot_sync(0xffffffffu, avA0 != 0.f);
    const unsigned mA1 = __ballot_sync(0xffffffffu, avA1 != 0.f);
    const unsigned mB0 = __ballot_sync(0xffffffffu, avB0 != 0.f);
    const unsigned mB1 = __ballot_sync(0xffffffffu, avB1 != 0.f);

    __syncthreads();

    // ------------------------------------------------------------------
    // Stage 2: msg1 (full). Compacted sparse gather; e and U1 both in smem.
    // ------------------------------------------------------------------
    #pragma unroll
    for (int r = 0; r < 2; r++) {
        const int row = row0 + r;
        const float m = s.maskv[row];
        float av0 = r ? avB0 : avA0;
        float av1 = r ? avB1 : avA1;
        unsigned nz0 = r ? mB0 : mA0;
        unsigned nz1 = r ? mB1 : mA1;
        float acc = 0.f;
        if (m != 0.f) {
            const float4* erow = (const float4*)&s.esh[row][0][0];
            while (nz0) {
                int j = __ffs(nz0) - 1; nz0 &= nz0 - 1;
                float av = __shfl_sync(0xffffffffu, av0, j);
                float4 ev = erow[j];
                acc += (av*ev.x) * s.U1[j][0][lane];
                acc += (av*ev.y) * s.U1[j][1][lane];
                acc += (av*ev.z) * s.U1[j][2][lane];
                acc += (av*ev.w) * s.U1[j][3][lane];
                acc +=  av       * s.U1[j][4][lane];
            }
            while (nz1) {
                int j = __ffs(nz1) - 1; nz1 &= nz1 - 1;
                int i = 32 + j;
                float av = __shfl_sync(0xffffffffu, av1, j);
                float4 ev = erow[i];
                acc += (av*ev.x) * s.U1[i][0][lane];
                acc += (av*ev.y) * s.U1[i][1][lane];
                acc += (av*ev.z) * s.U1[i][2][lane];
                acc += (av*ev.w) * s.U1[i][3][lane];
                acc +=  av       * s.U1[i][4][lane];
            }
        }
        s.h1[row][lane] = fmaxf((acc + s.root1[row][lane]) * m, 0.f);
    }
    __syncthreads();

    // ------------------------------------------------------------------
    // Stage 3: prep2 (slice). Warp owns rows (2w, 2w+1).
    // Main acc: lane = s*8+xl computes U2[row][s][xl].
    // Aux acc: lanes split by (lane>>4) into the two rows; (lane&15):
    //          0..7 bias-kernel slot, 8..15 root2.
    // ------------------------------------------------------------------
    {
        float h0  = s.h1[row0][lane];
        float h1v = s.h1[row1][lane];
        float accA = 0.f, accB = 0.f;
        float acc2 = ((lane & 15) >= 8) ? s.bs2s[lane & 7] : 0.f;
        #pragma unroll
        for (int y = 0; y < C_; y++) {
            float w   = s.w2s[y][lane];
            float hv0 = __shfl_sync(0xffffffffu, h0,  y);
            float hv1 = __shfl_sync(0xffffffffu, h1v, y);
            accA += w * hv0;
            accB += w * hv1;
            float wbr  = s.w2br[y][lane & 15];
            float hsel = (lane < 16) ? hv0 : hv1;
            acc2 += wbr * hsel;
        }
        s.U2[row0][lane] = accA;
        s.U2[row1][lane] = accB;
        s.U2br[row0 + (lane >> 4)][lane & 15] = acc2;
    }
    __syncthreads();

    // ------------------------------------------------------------------
    // Stage 4: msg2 (slice) + fused pool partial.
    // lane = s-group (lane>>3) x channel (lane&7).
    // ------------------------------------------------------------------
    float pacc = 0.f;
    const float wdv  = wd[g*XL_ + (lane & 7)];
    const int   sidx = lane >> 3;
    #pragma unroll
    for (int r = 0; r < 2; r++) {
        const int row = row0 + r;
        const float m = s.maskv[row];
        float av0 = r ? avB0 : avA0;
        float av1 = r ? avB1 : avA1;
        unsigned nz0 = r ? mB0 : mA0;
        unsigned nz1 = r ? mB1 : mA1;
        float acc = 0.f, accb = 0.f;
        if (m != 0.f) {
            const float* erowf = &s.esh[row][0][0];
            while (nz0) {
                int j = __ffs(nz0) - 1; nz0 &= nz0 - 1;
                float av = __shfl_sync(0xffffffffu, av0, j);
                float ev = erowf[j*S_ + sidx];
                acc  += (av*ev) * s.U2[j][lane];
                accb +=  av     * s.U2br[j][lane & 7];
            }
            while (nz1) {
                int j = __ffs(nz1) - 1; nz1 &= nz1 - 1;
                int i = 32 + j;
                float av = __shfl_sync(0xffffffffu, av1, j);
                float ev = erowf[i*S_ + sidx];
                acc  += (av*ev) * s.U2[i][lane];
                accb +=  av     * s.U2br[i][lane & 7];
            }
        }
        // fold the 4 s-groups (accb is already identical across groups)
        acc += __shfl_xor_sync(0xffffffffu, acc, 8);
        acc += __shfl_xor_sync(0xffffffffu, acc, 16);
        float rt  = s.U2br[row][8 + (lane & 7)];
        float val = fmaxf((acc + accb + rt) * m, 0.f);
        if (lane < 8) pacc += val * wdv;     // count each channel once
    }

    // block-reduce pool partial
    #pragma unroll
    for (int off = 16; off > 0; off >>= 1)
        pacc += __shfl_down_sync(0xffffffffu, pacc, off);
    if (lane == 0) s.red[warp] = pacc;
    __syncthreads();
    if (warp == 0) {
        float v = s.red[lane];
        #pragma unroll
        for (int off = 16; off > 0; off >>= 1)
            v += __shfl_down_sync(0xffffffffu, v, off);
        if (lane == 0) {
            g_part[b*G_ + g] = v;
            __threadfence();
            unsigned t = atomicInc(&g_cnt[b], G_ - 1u);   // wraps to 0 each call
            if (t == G_ - 1u) {
                volatile float* p = g_part + b*G_;
                out[b] = p[0] + p[1] + p[2] + p[3] + bd[0];
            }
        }
    }
}

// ---------------------------------------------------------------------------
extern "C" void kernel_launch(void* const* d_in, const int* in_sizes, int n_in,
                              void* d_out, int out_size)
{
    const float* x       = (const float*)d_in[0];
    const float* a       = (const float*)d_in[1];
    const float* e       = (const float*)d_in[2];
    const float* w1_kern = (const float*)d_in[3];
    const float* b1_kern = (const float*)d_in[4];
    const float* w1_root = (const float*)d_in[5];
    const float* b1      = (const float*)d_in[6];
    const float* w2_kern = (const float*)d_in[7];
    const float* b2_kern = (const float*)d_in[8];
    const float* w2_root = (const float*)d_in[9];
    const float* b2      = (const float*)d_in[10];
    const float* w_dense = (const float*)d_in[11];
    const float* b_dense = (const float*)d_in[12];
    float* out = (float*)d_out;

    cudaFuncSetAttribute(fused_gnn_kernel,
                         cudaFuncAttributeMaxDynamicSharedMemorySize,
                         (int)sizeof(Smem));

    fused_gnn_kernel<<<B_*G_, 1024, sizeof(Smem)>>>(
        x, a, e,
        w1_kern, b1_kern, w1_root, b1,
        w2_kern, b2_kern, w2_root, b2,
        w_dense, b_dense, out);
}

// round 6
// speedup vs baseline: 1.3433x; 1.3433x over previous
#include <cuda_runtime.h>

// Problem constants
#define B_  16
#define N_  64
#define S_  4
#define F0_ 8
#define C_  32
#define G_  8          // CTAs per batch (channel slices)
#define XL_ 4          // channels per slice (C_/G_)

// Cross-CTA pool combine scratch
__device__ float    g_part[B_ * G_];
__device__ unsigned g_cnt[B_];        // zero-init; atomicInc wraps -> 0 each call

// Per-CTA shared workspace (~73 KB)
struct alignas(16) Smem {
    float wT1[F0_][5][C_];   // layer1 kernel weights transposed [y][s][x] (s=4: b1_kern)
    float wrs1[F0_][C_];     // layer1 root weights [y][x]
    float U1[N_][5][C_];     // layer1 per-node projections (full)
    float root1[N_][C_];
    float h1[N_][C_];
    float w2s[C_][16];       // layer2 kernel slice [y][s*4+xl]
    float w2br[C_][8];       // [y][0..3: b2_kern slice, 4..7: w2_root slice]
    float U2[N_][16];        // [i][s*4+xl]
    float U2br[N_][8];       // [i][0..3: bias-kernel slot, 4..7: root2]
    float bs1[C_];
    float bs2s[XL_];
    float maskv[N_];
    float red[32];
};

__global__ __launch_bounds__(1024, 1)
void fused_gnn_kernel(const float* __restrict__ x,
                      const float* __restrict__ a,
                      const float* __restrict__ e,
                      const float* __restrict__ w1k, const float* __restrict__ b1k,
                      const float* __restrict__ w1r, const float* __restrict__ b1,
                      const float* __restrict__ w2k, const float* __restrict__ b2k,
                      const float* __restrict__ w2r, const float* __restrict__ b2,
                      const float* __restrict__ wd,  const float* __restrict__ bd,
                      float* __restrict__ out)
{
    extern __shared__ Smem smem[];
    Smem& s = *smem;

    const int b    = blockIdx.x >> 3;     // batch
    const int g    = blockIdx.x & 7;      // channel slice
    const int tid  = threadIdx.x;
    const int warp = tid >> 5;
    const int lane = tid & 31;

    const float* xb = x + (size_t)b * N_ * (F0_ + 1);
    const float* ab = a + (size_t)b * N_ * N_;
    const float* eb = e + (size_t)b * N_ * N_ * S_;

    // ------------------------------------------------------------------
    // Early hoist: adjacency for this warp's two rows (reused by msg1+msg2).
    // Issued first so the gmem latency overlaps weight staging.
    // ------------------------------------------------------------------
    const int row0 = warp*2, row1 = row0 + 1;
    const float avA0 = ab[(size_t)row0*N_ + lane];
    const float avA1 = ab[(size_t)row0*N_ + 32 + lane];
    const float avB0 = ab[(size_t)row1*N_ + lane];
    const float avB1 = ab[(size_t)row1*N_ + 32 + lane];

    // ------------------------------------------------------------------
    // Stage 0: weight staging
    // ------------------------------------------------------------------
    for (int i0 = tid; i0 < S_*C_*F0_; i0 += 1024) {
        int sI = i0 / (C_*F0_); int r = i0 - sI*(C_*F0_);
        int xx = r / F0_;       int yy = r - xx*F0_;
        s.wT1[yy][sI][xx] = w1k[i0];
    }
    for (int i0 = tid; i0 < C_*F0_; i0 += 1024) {
        int xx = i0 / F0_, yy = i0 - xx*F0_;
        s.wT1[yy][4][xx] = b1k[i0];
    }
    for (int i0 = tid; i0 < F0_*C_; i0 += 1024)
        (&s.wrs1[0][0])[i0] = w1r[i0];

    // layer2 kernel slice: w2s[y][s*4+xl] = w2k[s*(C*C) + (g*4+xl)*C + y]
    if (tid < C_*16) {
        int yy = tid & 31, l = tid >> 5;      // l = s*4+xl in 0..15
        int sI = l >> 2,   xl = l & 3;
        s.w2s[yy][l] = w2k[sI*(C_*C_) + (g*XL_ + xl)*C_ + yy];
    }
    // layer2 bias-kernel + root slice
    if (tid < C_*8) {
        int yy = tid & 31, l = tid >> 5;      // l in 0..7
        float v;
        if (l < 4) v = b2k[(g*XL_ + l)*C_ + yy];           // bias-kernel slot
        else       v = w2r[yy*C_ + g*XL_ + (l - 4)];       // root weights
        s.w2br[yy][l] = v;
    }
    if (tid < XL_) s.bs2s[tid] = b2[g*XL_ + tid];
    if (tid < C_)  s.bs1[tid]  = b1[tid];

    const unsigned mA0 = __ballot_sync(0xffffffffu, avA0 != 0.f);
    const unsigned mA1 = __ballot_sync(0xffffffffu, avA1 != 0.f);
    const unsigned mB0 = __ballot_sync(0xffffffffu, avB0 != 0.f);
    const unsigned mB1 = __ballot_sync(0xffffffffu, avB1 != 0.f);
    __syncthreads();

    // ------------------------------------------------------------------
    // Stage 1: prep1 (full, redundant per slice-CTA). 2 rows/warp, lane=x.
    // ------------------------------------------------------------------
    #pragma unroll
    for (int r = 0; r < 2; r++) {
        const int row = row0 + r;
        float xv = (lane <= F0_) ? xb[row*(F0_+1) + lane] : 0.f;
        if (lane == F0_) s.maskv[row] = xv;

        float a0=0.f, a1=0.f, a2=0.f, a3=0.f, a4=0.f;
        float rt = s.bs1[lane];
        #pragma unroll
        for (int y = 0; y < F0_; y++) {
            float hv = __shfl_sync(0xffffffffu, xv, y);
            a0 += s.wT1[y][0][lane] * hv;
            a1 += s.wT1[y][1][lane] * hv;
            a2 += s.wT1[y][2][lane] * hv;
            a3 += s.wT1[y][3][lane] * hv;
            a4 += s.wT1[y][4][lane] * hv;
            rt += s.wrs1[y][lane]   * hv;
        }
        s.U1[row][0][lane] = a0;
        s.U1[row][1][lane] = a1;
        s.U1[row][2][lane] = a2;
        s.U1[row][3][lane] = a3;
        s.U1[row][4][lane] = a4;
        s.root1[row][lane] = rt;
    }
    __syncthreads();

    // ------------------------------------------------------------------
    // Stage 2: msg1 (full). Compacted sparse gather; e from gmem (L2-hot),
    // U1 in smem.
    // ------------------------------------------------------------------
    #pragma unroll
    for (int r = 0; r < 2; r++) {
        const int row = row0 + r;
        const float m = s.maskv[row];
        float av0 = r ? avB0 : avA0;
        float av1 = r ? avB1 : avA1;
        unsigned nz0 = r ? mB0 : mA0;
        unsigned nz1 = r ? mB1 : mA1;
        float acc = 0.f;
        if (m != 0.f) {
            const float4* erow = (const float4*)(eb + (size_t)row * N_ * S_);
            while (nz0) {
                int j = __ffs(nz0) - 1; nz0 &= nz0 - 1;
                float av = __shfl_sync(0xffffffffu, av0, j);
                float4 ev = erow[j];
                acc += (av*ev.x) * s.U1[j][0][lane];
                acc += (av*ev.y) * s.U1[j][1][lane];
                acc += (av*ev.z) * s.U1[j][2][lane];
                acc += (av*ev.w) * s.U1[j][3][lane];
                acc +=  av       * s.U1[j][4][lane];
            }
            while (nz1) {
                int j = __ffs(nz1) - 1; nz1 &= nz1 - 1;
                int i = 32 + j;
                float av = __shfl_sync(0xffffffffu, av1, j);
                float4 ev = erow[i];
                acc += (av*ev.x) * s.U1[i][0][lane];
                acc += (av*ev.y) * s.U1[i][1][lane];
                acc += (av*ev.z) * s.U1[i][2][lane];
                acc += (av*ev.w) * s.U1[i][3][lane];
                acc +=  av       * s.U1[i][4][lane];
            }
        }
        s.h1[row][lane] = fmaxf((acc + s.root1[row][lane]) * m, 0.f);
    }
    __syncthreads();

    // ------------------------------------------------------------------
    // Stage 3: prep2 (slice, both rows at once).
    // Main: lanes 0-15 -> row0, 16-31 -> row1; l = lane&15 = s*4+xl.
    //   U2[rowsel][l] = sum_y w2s[y][l] * h1[rowsel][y]
    // Aux (lanes 0-15 only store): l2 = lane&7 (0..3 bias-kernel, 4..7 root),
    //   rowsel2 = row0 + ((lane>>3)&1).
    // h1 read as lane-uniform float4 LDS (2 distinct addrs -> broadcast).
    // ------------------------------------------------------------------
    {
        const int l   = lane & 15;
        const int l2  = lane & 7;
        const int rowsel  = row0 + (lane >> 4);
        const int rowsel2 = row0 + ((lane >> 3) & 1);
        float acc  = 0.f;
        float acc2 = (l2 >= 4) ? s.bs2s[l2 & 3] : 0.f;
        #pragma unroll
        for (int y0 = 0; y0 < C_; y0 += 4) {
            float4 hm = *(const float4*)&s.h1[rowsel][y0];
            float4 ha = *(const float4*)&s.h1[rowsel2][y0];
            acc  += s.w2s[y0+0][l] * hm.x;
            acc  += s.w2s[y0+1][l] * hm.y;
            acc  += s.w2s[y0+2][l] * hm.z;
            acc  += s.w2s[y0+3][l] * hm.w;
            acc2 += s.w2br[y0+0][l2] * ha.x;
            acc2 += s.w2br[y0+1][l2] * ha.y;
            acc2 += s.w2br[y0+2][l2] * ha.z;
            acc2 += s.w2br[y0+3][l2] * ha.w;
        }
        s.U2[rowsel][l] = acc;
        if (lane < 16) s.U2br[rowsel2][l2] = acc2;
    }
    __syncthreads();

    // ------------------------------------------------------------------
    // Stage 4: msg2 (slice) + fused pool partial.
    // l = lane&15 = sidx*4 + xl (upper 16 lanes duplicate; harmless).
    // ------------------------------------------------------------------
    float pacc = 0.f;
    const int   l    = lane & 15;
    const int   sidx = l >> 2;
    const int   xl   = l & 3;
    const float wdv  = wd[g*XL_ + xl];
    #pragma unroll
    for (int r = 0; r < 2; r++) {
        const int row = row0 + r;
        const float m = s.maskv[row];
        float av0 = r ? avB0 : avA0;
        float av1 = r ? avB1 : avA1;
        unsigned nz0 = r ? mB0 : mA0;
        unsigned nz1 = r ? mB1 : mA1;
        float acc = 0.f, accb = 0.f;
        if (m != 0.f) {
            const float* erowf = eb + (size_t)row * N_ * S_;
            while (nz0) {
                int j = __ffs(nz0) - 1; nz0 &= nz0 - 1;
                float av = __shfl_sync(0xffffffffu, av0, j);
                float ev = erowf[j*S_ + sidx];
                acc  += (av*ev) * s.U2[j][l];
                accb +=  av     * s.U2br[j][xl];
            }
            while (nz1) {
                int j = __ffs(nz1) - 1; nz1 &= nz1 - 1;
                int i = 32 + j;
                float av = __shfl_sync(0xffffffffu, av1, j);
                float ev = erowf[i*S_ + sidx];
                acc  += (av*ev) * s.U2[i][l];
                accb +=  av     * s.U2br[i][xl];
            }
        }
        // fold the 4 s-groups (sidx lives in bits 2..3 of l)
        acc += __shfl_xor_sync(0xffffffffu, acc, 4);
        acc += __shfl_xor_sync(0xffffffffu, acc, 8);
        float rt  = s.U2br[row][4 + xl];
        float val = fmaxf((acc + accb + rt) * m, 0.f);
        if (lane < XL_) pacc += val * wdv;     // count each channel once
    }

    // block-reduce pool partial
    #pragma unroll
    for (int off = 16; off > 0; off >>= 1)
        pacc += __shfl_down_sync(0xffffffffu, pacc, off);
    if (lane == 0) s.red[warp] = pacc;
    __syncthreads();
    if (warp == 0) {
        float v = s.red[lane];
        #pragma unroll
        for (int off = 16; off > 0; off >>= 1)
            v += __shfl_down_sync(0xffffffffu, v, off);
        if (lane == 0) {
            g_part[b*G_ + g] = v;
            __threadfence();
            unsigned t = atomicInc(&g_cnt[b], G_ - 1u);   // wraps to 0 each call
            if (t == G_ - 1u) {
                volatile float* p = g_part + b*G_;
                float sum = bd[0];
                #pragma unroll
                for (int k = 0; k < G_; k++) sum += p[k];
                out[b] = sum;
            }
        }
    }
}

// ---------------------------------------------------------------------------
extern "C" void kernel_launch(void* const* d_in, const int* in_sizes, int n_in,
                              void* d_out, int out_size)
{
    const float* x       = (const float*)d_in[0];
    const float* a       = (const float*)d_in[1];
    const float* e       = (const float*)d_in[2];
    const float* w1_kern = (const float*)d_in[3];
    const float* b1_kern = (const float*)d_in[4];
    const float* w1_root = (const float*)d_in[5];
    const float* b1      = (const float*)d_in[6];
    const float* w2_kern = (const float*)d_in[7];
    const float* b2_kern = (const float*)d_in[8];
    const float* w2_root = (const float*)d_in[9];
    const float* b2      = (const float*)d_in[10];
    const float* w_dense = (const float*)d_in[11];
    const float* b_dense = (const float*)d_in[12];
    float* out = (float*)d_out;

    cudaFuncSetAttribute(fused_gnn_kernel,
                         cudaFuncAttributeMaxDynamicSharedMemorySize,
                         (int)sizeof(Smem));

    fused_gnn_kernel<<<B_*G_, 1024, sizeof(Smem)>>>(
        x, a, e,
        w1_kern, b1_kern, w1_root, b1,
        w2_kern, b2_kern, w2_root, b2,
        w_dense, b_dense, out);
}

// round 7
// speedup vs baseline: 1.5254x; 1.1356x over previous
#include <cuda_runtime.h>

// Problem constants
#define B_  16
#define N_  64
#define S_  4
#define F0_ 8
#define C_  32
#define G_  8          // CTAs per batch (channel slices)
#define XL_ 4          // channels per slice (C_/G_)

// Cross-CTA pool combine scratch
__device__ float    g_part[B_ * G_];
__device__ unsigned g_cnt[B_];        // zero-init; atomicInc wraps -> 0 each call

// Per-CTA shared workspace (~64 KB)
struct alignas(16) Smem {
    float wT1[F0_][5][C_];   // layer1 kernel weights transposed [y][s][x] (s=4: b1_kern)
    float wrs1[F0_][C_];     // layer1 root weights [y][x]
    float U1[N_][5][C_];     // layer1 per-node projections (full)   (40 KB)
    float h1[N_][C_];        // layer1 activations                    (8 KB)
    float w2s[C_][16];       // layer2 kernel slice [y][s*4+xl]
    float w2br[C_][8];       // [y][0..3: b2_kern slice, 4..7: w2_root slice]
    float U2[N_][16];        // [i][s*4+xl]
    float U2br[N_][8];       // [i][0..3: bias-kernel slot, 4..7: root2]
    float bs1[C_];
    float bs2s[XL_];
    float red[32];
};

__global__ __launch_bounds__(1024, 1)
void fused_gnn_kernel(const float* __restrict__ x,
                      const float* __restrict__ a,
                      const float* __restrict__ e,
                      const float* __restrict__ w1k, const float* __restrict__ b1k,
                      const float* __restrict__ w1r, const float* __restrict__ b1,
                      const float* __restrict__ w2k, const float* __restrict__ b2k,
                      const float* __restrict__ w2r, const float* __restrict__ b2,
                      const float* __restrict__ wd,  const float* __restrict__ bd,
                      float* __restrict__ out)
{
    extern __shared__ Smem smem[];
    Smem& s = *smem;

    const int b    = blockIdx.x >> 3;     // batch
    const int g    = blockIdx.x & 7;      // channel slice
    const int tid  = threadIdx.x;
    const int warp = tid >> 5;
    const int lane = tid & 31;

    const float* xb = x + (size_t)b * N_ * (F0_ + 1);
    const float* ab = a + (size_t)b * N_ * N_;
    const float* eb = e + (size_t)b * N_ * N_ * S_;

    const int row0 = warp*2, row1 = row0 + 1;

    // ------------------------------------------------------------------
    // Early loads (overlap with staging): adjacency (only its nonzero
    // PATTERN matters — a is exactly 0/1 and e is pre-masked by a), and
    // this warp's two x-rows packed into one register:
    //   lanes 0..8  -> x[row0][0..8], lanes 16..24 -> x[row1][0..8]
    // ------------------------------------------------------------------
    const float avA0 = ab[(size_t)row0*N_ + lane];
    const float avA1 = ab[(size_t)row0*N_ + 32 + lane];
    const float avB0 = ab[(size_t)row1*N_ + lane];
    const float avB1 = ab[(size_t)row1*N_ + 32 + lane];

    const int rhalf = lane >> 4;
    const int cc    = lane & 15;
    float xv01 = 0.f;
    if (cc <= F0_) xv01 = xb[(row0 + rhalf)*(F0_+1) + cc];

    // ------------------------------------------------------------------
    // Stage 0: weight staging
    // ------------------------------------------------------------------
    for (int i0 = tid; i0 < S_*C_*F0_; i0 += 1024) {
        int sI = i0 / (C_*F0_); int r = i0 - sI*(C_*F0_);
        int xx = r / F0_;       int yy = r - xx*F0_;
        s.wT1[yy][sI][xx] = w1k[i0];
    }
    if (tid < C_*F0_) {
        int xx = tid / F0_, yy = tid - xx*F0_;
        s.wT1[yy][4][xx] = b1k[tid];
    }
    if (tid < F0_*C_)
        (&s.wrs1[0][0])[tid] = w1r[tid];

    // layer2 kernel slice: w2s[y][s*4+xl] = w2k[s*(C*C) + (g*4+xl)*C + y]
    if (tid < C_*16) {
        int yy = tid & 31, l = tid >> 5;      // l = s*4+xl in 0..15
        int sI = l >> 2,   xl = l & 3;
        s.w2s[yy][l] = w2k[sI*(C_*C_) + (g*XL_ + xl)*C_ + yy];
    }
    // layer2 bias-kernel + root slice
    if (tid < C_*8) {
        int yy = tid & 31, l = tid >> 5;      // l in 0..7
        float v;
        if (l < 4) v = b2k[(g*XL_ + l)*C_ + yy];           // bias-kernel slot
        else       v = w2r[yy*C_ + g*XL_ + (l - 4)];       // root weights
        s.w2br[yy][l] = v;
    }
    if (tid < XL_) s.bs2s[tid] = b2[g*XL_ + tid];
    if (tid < C_)  s.bs1[tid]  = b1[tid];

    // Nonzero masks + row masks (register-resident, reused by msg1 & msg2)
    const unsigned mA0 = __ballot_sync(0xffffffffu, avA0 != 0.f);
    const unsigned mA1 = __ballot_sync(0xffffffffu, avA1 != 0.f);
    const unsigned mB0 = __ballot_sync(0xffffffffu, avB0 != 0.f);
    const unsigned mB1 = __ballot_sync(0xffffffffu, avB1 != 0.f);
    const float m0 = __shfl_sync(0xffffffffu, xv01, F0_);
    const float m1 = __shfl_sync(0xffffffffu, xv01, 16 + F0_);
    __syncthreads();

    // ------------------------------------------------------------------
    // Stage 1: prep1 (full, redundant per slice-CTA). Both rows share the
    // per-y weight loads; lane = x channel. root terms stay in registers.
    // ------------------------------------------------------------------
    float rt0, rt1;
    {
        float u00=0.f,u01=0.f,u02=0.f,u03=0.f,u04=0.f;
        float u10=0.f,u11=0.f,u12=0.f,u13=0.f,u14=0.f;
        float bsv = s.bs1[lane];
        rt0 = bsv; rt1 = bsv;
        #pragma unroll
        for (int y = 0; y < F0_; y++) {
            float hv0 = __shfl_sync(0xffffffffu, xv01, y);
            float hv1 = __shfl_sync(0xffffffffu, xv01, 16 + y);
            float w0 = s.wT1[y][0][lane];
            float w1 = s.wT1[y][1][lane];
            float w2 = s.wT1[y][2][lane];
            float w3 = s.wT1[y][3][lane];
            float w4 = s.wT1[y][4][lane];
            float wr = s.wrs1[y][lane];
            u00 += w0*hv0; u01 += w1*hv0; u02 += w2*hv0;
            u03 += w3*hv0; u04 += w4*hv0; rt0 += wr*hv0;
            u10 += w0*hv1; u11 += w1*hv1; u12 += w2*hv1;
            u13 += w3*hv1; u14 += w4*hv1; rt1 += wr*hv1;
        }
        s.U1[row0][0][lane] = u00;
        s.U1[row0][1][lane] = u01;
        s.U1[row0][2][lane] = u02;
        s.U1[row0][3][lane] = u03;
        s.U1[row0][4][lane] = u04;
        s.U1[row1][0][lane] = u10;
        s.U1[row1][1][lane] = u11;
        s.U1[row1][2][lane] = u12;
        s.U1[row1][3][lane] = u13;
        s.U1[row1][4][lane] = u14;
    }
    __syncthreads();

    // ------------------------------------------------------------------
    // Stage 2: msg1 (full). Compacted gather; a==1 at every visited edge,
    // so no adjacency multiplies. e from gmem (L2-hot), U1 in smem.
    // ------------------------------------------------------------------
    {
        float acc0 = 0.f, acc1 = 0.f;
        const float4* erow0 = (const float4*)(eb + (size_t)row0 * N_ * S_);
        const float4* erow1 = (const float4*)(eb + (size_t)row1 * N_ * S_);
        unsigned nz;
        nz = mA0;
        while (nz) {
            int j = __ffs(nz) - 1; nz &= nz - 1;
            float4 ev = erow0[j];
            acc0 += ev.x * s.U1[j][0][lane];
            acc0 += ev.y * s.U1[j][1][lane];
            acc0 += ev.z * s.U1[j][2][lane];
            acc0 += ev.w * s.U1[j][3][lane];
            acc0 +=        s.U1[j][4][lane];
        }
        nz = mA1;
        while (nz) {
            int j = __ffs(nz) - 1; nz &= nz - 1;
            int i = 32 + j;
            float4 ev = erow0[i];
            acc0 += ev.x * s.U1[i][0][lane];
            acc0 += ev.y * s.U1[i][1][lane];
            acc0 += ev.z * s.U1[i][2][lane];
            acc0 += ev.w * s.U1[i][3][lane];
            acc0 +=        s.U1[i][4][lane];
        }
        nz = mB0;
        while (nz) {
            int j = __ffs(nz) - 1; nz &= nz - 1;
            float4 ev = erow1[j];
            acc1 += ev.x * s.U1[j][0][lane];
            acc1 += ev.y * s.U1[j][1][lane];
            acc1 += ev.z * s.U1[j][2][lane];
            acc1 += ev.w * s.U1[j][3][lane];
            acc1 +=        s.U1[j][4][lane];
        }
        nz = mB1;
        while (nz) {
            int j = __ffs(nz) - 1; nz &= nz - 1;
            int i = 32 + j;
            float4 ev = erow1[i];
            acc1 += ev.x * s.U1[i][0][lane];
            acc1 += ev.y * s.U1[i][1][lane];
            acc1 += ev.z * s.U1[i][2][lane];
            acc1 += ev.w * s.U1[i][3][lane];
            acc1 +=        s.U1[i][4][lane];
        }
        s.h1[row0][lane] = fmaxf(acc0 + rt0, 0.f) * m0;
        s.h1[row1][lane] = fmaxf(acc1 + rt1, 0.f) * m1;
    }
    __syncwarp();   // h1 produced & consumed by this warp only

    // ------------------------------------------------------------------
    // Stage 3: prep2 (slice, both rows at once).
    // lanes 0-15 -> row0, 16-31 -> row1; l = lane&15 = s*4+xl.
    // Aux accumulator (lanes 0-15 store): l2 = lane&7, rowsel2 per bit 3.
    // h1 read as lane-uniform float4 LDS (2 distinct addrs -> broadcast).
    // ------------------------------------------------------------------
    {
        const int l   = lane & 15;
        const int l2  = lane & 7;
        const int rowsel  = row0 + rhalf;
        const int rowsel2 = row0 + ((lane >> 3) & 1);
        float acc  = 0.f;
        float acc2 = (l2 >= 4) ? s.bs2s[l2 & 3] : 0.f;
        #pragma unroll
        for (int y0 = 0; y0 < C_; y0 += 4) {
            float4 hm = *(const float4*)&s.h1[rowsel][y0];
            float4 ha = *(const float4*)&s.h1[rowsel2][y0];
            acc  += s.w2s[y0+0][l] * hm.x;
            acc  += s.w2s[y0+1][l] * hm.y;
            acc  += s.w2s[y0+2][l] * hm.z;
            acc  += s.w2s[y0+3][l] * hm.w;
            acc2 += s.w2br[y0+0][l2] * ha.x;
            acc2 += s.w2br[y0+1][l2] * ha.y;
            acc2 += s.w2br[y0+2][l2] * ha.z;
            acc2 += s.w2br[y0+3][l2] * ha.w;
        }
        s.U2[rowsel][l] = acc;
        if (lane < 16) s.U2br[rowsel2][l2] = acc2;
    }
    __syncthreads();

    // ------------------------------------------------------------------
    // Stage 4: msg2 (slice) + fused pool partial.
    // l = lane&15 = sidx*4 + xl (upper 16 lanes duplicate; harmless).
    // ------------------------------------------------------------------
    float pacc = 0.f;
    {
        const int   l    = lane & 15;
        const int   sidx = (lane >> 2) & 3;
        const int   xl   = lane & 3;
        const float wdv  = wd[g*XL_ + xl];
        #pragma unroll
        for (int r = 0; r < 2; r++) {
            const int row = row0 + r;
            const float m = r ? m1 : m0;
            unsigned nz0 = r ? mB0 : mA0;
            unsigned nz1 = r ? mB1 : mA1;
            float acc = 0.f, accb = 0.f;
            const float* erowf = eb + (size_t)row * N_ * S_;
            while (nz0) {
                int j = __ffs(nz0) - 1; nz0 &= nz0 - 1;
                acc  += erowf[j*S_ + sidx] * s.U2[j][l];
                accb += s.U2br[j][xl];
            }
            while (nz1) {
                int j = __ffs(nz1) - 1; nz1 &= nz1 - 1;
                int i = 32 + j;
                acc  += erowf[i*S_ + sidx] * s.U2[i][l];
                accb += s.U2br[i][xl];
            }
            // fold the 4 s-groups (sidx lives in bits 2..3 of lane)
            acc += __shfl_xor_sync(0xffffffffu, acc, 4);
            acc += __shfl_xor_sync(0xffffffffu, acc, 8);
            float rt  = s.U2br[row][4 + xl];
            float val = fmaxf(acc + accb + rt, 0.f) * m;
            if (lane < XL_) pacc += val * wdv;   // count each channel once
        }
    }

    // block-reduce pool partial
    #pragma unroll
    for (int off = 16; off > 0; off >>= 1)
        pacc += __shfl_down_sync(0xffffffffu, pacc, off);
    if (lane == 0) s.red[warp] = pacc;
    __syncthreads();
    if (warp == 0) {
        float v = s.red[lane];
        #pragma unroll
        for (int off = 16; off > 0; off >>= 1)
            v += __shfl_down_sync(0xffffffffu, v, off);
        if (lane == 0) {
            g_part[b*G_ + g] = v;
            __threadfence();
            unsigned t = atomicInc(&g_cnt[b], G_ - 1u);   // wraps to 0 each call
            if (t == G_ - 1u) {
                volatile float* p = g_part + b*G_;
                float sum = bd[0];
                #pragma unroll
                for (int k = 0; k < G_; k++) sum += p[k];
                out[b] = sum;
            }
        }
    }
}

// ---------------------------------------------------------------------------
extern "C" void kernel_launch(void* const* d_in, const int* in_sizes, int n_in,
                              void* d_out, int out_size)
{
    const float* x       = (const float*)d_in[0];
    const float* a       = (const float*)d_in[1];
    const float* e       = (const float*)d_in[2];
    const float* w1_kern = (const float*)d_in[3];
    const float* b1_kern = (const float*)d_in[4];
    const float* w1_root = (const float*)d_in[5];
    const float* b1      = (const float*)d_in[6];
    const float* w2_kern = (const float*)d_in[7];
    const float* b2_kern = (const float*)d_in[8];
    const float* w2_root = (const float*)d_in[9];
    const float* b2      = (const float*)d_in[10];
    const float* w_dense = (const float*)d_in[11];
    const float* b_dense = (const float*)d_in[12];
    float* out = (float*)d_out;

    cudaFuncSetAttribute(fused_gnn_kernel,
                         cudaFuncAttributeMaxDynamicSharedMemorySize,
                         (int)sizeof(Smem));

    fused_gnn_kernel<<<B_*G_, 1024, sizeof(Smem)>>>(
        x, a, e,
        w1_kern, b1_kern, w1_root, b1,
        w2_kern, b2_kern, w2_root, b2,
        w_dense, b_dense, out);
}

// round 8
// speedup vs baseline: 1.6000x; 1.0489x over previous
#include <cuda_runtime.h>

// Problem constants
#define B_  16
#define N_  64
#define S_  4
#define F0_ 8
#define C_  32
#define G_  8          // CTAs per batch (channel slices)
#define XL_ 4          // channels per slice (C_/G_)

// Cross-CTA pool combine scratch
__device__ float    g_part[B_ * G_];
__device__ unsigned g_cnt[B_];        // zero-init; atomicInc wraps -> 0 each call

// Per-CTA shared workspace (~64 KB)
struct alignas(16) Smem {
    float wT1[F0_][5][C_];   // layer1 kernel weights transposed [y][s][x] (s=4: b1_kern)
    float wrs1[F0_][C_];     // layer1 root weights [y][x]
    float U1[N_][5][C_];     // layer1 per-node projections (full)   (40 KB)
    float h1[N_][C_];        // layer1 activations                    (8 KB)
    float w2s[C_][16];       // layer2 kernel slice [y][s*4+xl]
    float w2br[C_][8];       // [y][0..3: b2_kern slice, 4..7: w2_root slice]
    float U2[N_][16];        // [i][s*4+xl]
    float U2br[N_][8];       // [i][0..3: bias-kernel slot, 4..7: root2]
    float bs1[C_];
    float bs2s[XL_];
    float red[32];
};

__global__ __launch_bounds__(1024, 1)
void fused_gnn_kernel(const float* __restrict__ x,
                      const float* __restrict__ a,
                      const float* __restrict__ e,
                      const float* __restrict__ w1k, const float* __restrict__ b1k,
                      const float* __restrict__ w1r, const float* __restrict__ b1,
                      const float* __restrict__ w2k, const float* __restrict__ b2k,
                      const float* __restrict__ w2r, const float* __restrict__ b2,
                      const float* __restrict__ wd,  const float* __restrict__ bd,
                      float* __restrict__ out)
{
    extern __shared__ Smem smem[];
    Smem& s = *smem;

    const int b    = blockIdx.x >> 3;     // batch
    const int g    = blockIdx.x & 7;      // channel slice
    const int tid  = threadIdx.x;
    const int warp = tid >> 5;
    const int lane = tid & 31;

    const float* xb = x + (size_t)b * N_ * (F0_ + 1);
    const float* ab = a + (size_t)b * N_ * N_;
    const float* eb = e + (size_t)b * N_ * N_ * S_;

    const int row0 = warp*2, row1 = row0 + 1;

    // ------------------------------------------------------------------
    // Early loads (overlap with staging): adjacency pattern (a is exactly
    // 0/1 and e is pre-masked by a, so only the ballot bits are needed),
    // and this warp's two x-rows packed into one register:
    //   lanes 0..8 -> x[row0][0..8], lanes 16..24 -> x[row1][0..8]
    // ------------------------------------------------------------------
    const float avA0 = ab[(size_t)row0*N_ + lane];
    const float avA1 = ab[(size_t)row0*N_ + 32 + lane];
    const float avB0 = ab[(size_t)row1*N_ + lane];
    const float avB1 = ab[(size_t)row1*N_ + 32 + lane];

    const int rhalf = lane >> 4;
    const int cc    = lane & 15;
    float xv01 = 0.f;
    if (cc <= F0_) xv01 = xb[(row0 + rhalf)*(F0_+1) + cc];

    // Prefetch this warp's two e-rows (2 KB contiguous = 16 x 128B lines)
    // into L1 so the data-dependent loads in msg1/msg2 are L1 hits.
    if (lane < 16) {
        const char* p = (const char*)(eb + (size_t)row0 * N_ * S_) + lane * 128;
        asm volatile("prefetch.global.L1 [%0];" :: "l"(p));
    }

    // ------------------------------------------------------------------
    // Stage 0: weight staging
    // ------------------------------------------------------------------
    for (int i0 = tid; i0 < S_*C_*F0_; i0 += 1024) {
        int sI = i0 / (C_*F0_); int r = i0 - sI*(C_*F0_);
        int xx = r / F0_;       int yy = r - xx*F0_;
        s.wT1[yy][sI][xx] = w1k[i0];
    }
    if (tid < C_*F0_) {
        int xx = tid / F0_, yy = tid - xx*F0_;
        s.wT1[yy][4][xx] = b1k[tid];
    }
    if (tid < F0_*C_)
        (&s.wrs1[0][0])[tid] = w1r[tid];

    // layer2 kernel slice: w2s[y][s*4+xl] = w2k[s*(C*C) + (g*4+xl)*C + y]
    if (tid < C_*16) {
        int yy = tid & 31, l = tid >> 5;      // l = s*4+xl in 0..15
        int sI = l >> 2,   xl = l & 3;
        s.w2s[yy][l] = w2k[sI*(C_*C_) + (g*XL_ + xl)*C_ + yy];
    }
    // layer2 bias-kernel + root slice
    if (tid < C_*8) {
        int yy = tid & 31, l = tid >> 5;      // l in 0..7
        float v;
        if (l < 4) v = b2k[(g*XL_ + l)*C_ + yy];           // bias-kernel slot
        else       v = w2r[yy*C_ + g*XL_ + (l - 4)];       // root weights
        s.w2br[yy][l] = v;
    }
    if (tid < XL_) s.bs2s[tid] = b2[g*XL_ + tid];
    if (tid < C_)  s.bs1[tid]  = b1[tid];

    // Nonzero masks + row masks (register-resident, reused by msg1 & msg2)
    const unsigned mA0 = __ballot_sync(0xffffffffu, avA0 != 0.f);
    const unsigned mA1 = __ballot_sync(0xffffffffu, avA1 != 0.f);
    const unsigned mB0 = __ballot_sync(0xffffffffu, avB0 != 0.f);
    const unsigned mB1 = __ballot_sync(0xffffffffu, avB1 != 0.f);
    const float m0 = __shfl_sync(0xffffffffu, xv01, F0_);
    const float m1 = __shfl_sync(0xffffffffu, xv01, 16 + F0_);
    // If a row's mask is 0, no row t has a[t,row]!=0 (a includes valid_i),
    // so its U1/U2/h1 entries are never read: whole-warp skip when both
    // rows are masked (warp-uniform condition).
    const bool rows_live = (m0 != 0.f) || (m1 != 0.f);
    __syncthreads();

    // ------------------------------------------------------------------
    // Stage 1: prep1 (full, redundant per slice-CTA). Both rows share the
    // per-y weight loads; lane = x channel. root terms stay in registers.
    // ------------------------------------------------------------------
    float rt0 = 0.f, rt1 = 0.f;
    if (rows_live) {
        float u00=0.f,u01=0.f,u02=0.f,u03=0.f,u04=0.f;
        float u10=0.f,u11=0.f,u12=0.f,u13=0.f,u14=0.f;
        float bsv = s.bs1[lane];
        rt0 = bsv; rt1 = bsv;
        #pragma unroll
        for (int y = 0; y < F0_; y++) {
            float hv0 = __shfl_sync(0xffffffffu, xv01, y);
            float hv1 = __shfl_sync(0xffffffffu, xv01, 16 + y);
            float w0 = s.wT1[y][0][lane];
            float w1 = s.wT1[y][1][lane];
            float w2 = s.wT1[y][2][lane];
            float w3 = s.wT1[y][3][lane];
            float w4 = s.wT1[y][4][lane];
            float wr = s.wrs1[y][lane];
            u00 += w0*hv0; u01 += w1*hv0; u02 += w2*hv0;
            u03 += w3*hv0; u04 += w4*hv0; rt0 += wr*hv0;
            u10 += w0*hv1; u11 += w1*hv1; u12 += w2*hv1;
            u13 += w3*hv1; u14 += w4*hv1; rt1 += wr*hv1;
        }
        s.U1[row0][0][lane] = u00;
        s.U1[row0][1][lane] = u01;
        s.U1[row0][2][lane] = u02;
        s.U1[row0][3][lane] = u03;
        s.U1[row0][4][lane] = u04;
        s.U1[row1][0][lane] = u10;
        s.U1[row1][1][lane] = u11;
        s.U1[row1][2][lane] = u12;
        s.U1[row1][3][lane] = u13;
        s.U1[row1][4][lane] = u14;
    }
    __syncthreads();

    // ------------------------------------------------------------------
    // Stage 2: msg1 (full). Compacted gather; a==1 at every visited edge,
    // so no adjacency multiplies. e from gmem (L1 after prefetch), U1 smem.
    // ------------------------------------------------------------------
    if (rows_live) {
        float acc0 = 0.f, acc1 = 0.f;
        const float4* erow0 = (const float4*)(eb + (size_t)row0 * N_ * S_);
        const float4* erow1 = (const float4*)(eb + (size_t)row1 * N_ * S_);
        unsigned nz;
        nz = mA0;
        while (nz) {
            int j = __ffs(nz) - 1; nz &= nz - 1;
            float4 ev = erow0[j];
            acc0 += ev.x * s.U1[j][0][lane];
            acc0 += ev.y * s.U1[j][1][lane];
            acc0 += ev.z * s.U1[j][2][lane];
            acc0 += ev.w * s.U1[j][3][lane];
            acc0 +=        s.U1[j][4][lane];
        }
        nz = mA1;
        while (nz) {
            int j = __ffs(nz) - 1; nz &= nz - 1;
            int i = 32 + j;
            float4 ev = erow0[i];
            acc0 += ev.x * s.U1[i][0][lane];
            acc0 += ev.y * s.U1[i][1][lane];
            acc0 += ev.z * s.U1[i][2][lane];
            acc0 += ev.w * s.U1[i][3][lane];
            acc0 +=        s.U1[i][4][lane];
        }
        nz = mB0;
        while (nz) {
            int j = __ffs(nz) - 1; nz &= nz - 1;
            float4 ev = erow1[j];
            acc1 += ev.x * s.U1[j][0][lane];
            acc1 += ev.y * s.U1[j][1][lane];
            acc1 += ev.z * s.U1[j][2][lane];
            acc1 += ev.w * s.U1[j][3][lane];
            acc1 +=        s.U1[j][4][lane];
        }
        nz = mB1;
        while (nz) {
            int j = __ffs(nz) - 1; nz &= nz - 1;
            int i = 32 + j;
            float4 ev = erow1[i];
            acc1 += ev.x * s.U1[i][0][lane];
            acc1 += ev.y * s.U1[i][1][lane];
            acc1 += ev.z * s.U1[i][2][lane];
            acc1 += ev.w * s.U1[i][3][lane];
            acc1 +=        s.U1[i][4][lane];
        }
        s.h1[row0][lane] = fmaxf(acc0 + rt0, 0.f) * m0;
        s.h1[row1][lane] = fmaxf(acc1 + rt1, 0.f) * m1;
    }
    __syncwarp();   // h1 produced & consumed by this warp only

    // ------------------------------------------------------------------
    // Stage 3: prep2 (slice, both rows at once).
    // lanes 0-15 -> row0, 16-31 -> row1; l = lane&15 = s*4+xl.
    // Aux accumulator (lanes 0-15 store): l2 = lane&7, rowsel2 per bit 3.
    // h1 read as lane-uniform float4 LDS (2 distinct addrs -> broadcast).
    // ------------------------------------------------------------------
    if (rows_live) {
        const int l   = lane & 15;
        const int l2  = lane & 7;
        const int rowsel  = row0 + rhalf;
        const int rowsel2 = row0 + ((lane >> 3) & 1);
        float acc  = 0.f;
        float acc2 = (l2 >= 4) ? s.bs2s[l2 & 3] : 0.f;
        #pragma unroll
        for (int y0 = 0; y0 < C_; y0 += 4) {
            float4 hm = *(const float4*)&s.h1[rowsel][y0];
            float4 ha = *(const float4*)&s.h1[rowsel2][y0];
            acc  += s.w2s[y0+0][l] * hm.x;
            acc  += s.w2s[y0+1][l] * hm.y;
            acc  += s.w2s[y0+2][l] * hm.z;
            acc  += s.w2s[y0+3][l] * hm.w;
            acc2 += s.w2br[y0+0][l2] * ha.x;
            acc2 += s.w2br[y0+1][l2] * ha.y;
            acc2 += s.w2br[y0+2][l2] * ha.z;
            acc2 += s.w2br[y0+3][l2] * ha.w;
        }
        s.U2[rowsel][l] = acc;
        if (lane < 16) s.U2br[rowsel2][l2] = acc2;
    }
    __syncthreads();

    // ------------------------------------------------------------------
    // Stage 4: msg2 (slice) + fused pool partial.
    // l = lane&15 = sidx*4 + xl (upper 16 lanes duplicate; harmless).
    // ------------------------------------------------------------------
    float pacc = 0.f;
    if (rows_live) {
        const int   l    = lane & 15;
        const int   sidx = (lane >> 2) & 3;
        const int   xl   = lane & 3;
        const float wdv  = wd[g*XL_ + xl];
        #pragma unroll
        for (int r = 0; r < 2; r++) {
            const int row = row0 + r;
            const float m = r ? m1 : m0;
            unsigned nz0 = r ? mB0 : mA0;
            unsigned nz1 = r ? mB1 : mA1;
            float acc = 0.f, accb = 0.f;
            const float* erowf = eb + (size_t)row * N_ * S_;
            while (nz0) {
                int j = __ffs(nz0) - 1; nz0 &= nz0 - 1;
                acc  += erowf[j*S_ + sidx] * s.U2[j][l];
                accb += s.U2br[j][xl];
            }
            while (nz1) {
                int j = __ffs(nz1) - 1; nz1 &= nz1 - 1;
                int i = 32 + j;
                acc  += erowf[i*S_ + sidx] * s.U2[i][l];
                accb += s.U2br[i][xl];
            }
            // fold the 4 s-groups (sidx lives in bits 2..3 of lane)
            acc += __shfl_xor_sync(0xffffffffu, acc, 4);
            acc += __shfl_xor_sync(0xffffffffu, acc, 8);
            float rt  = s.U2br[row][4 + xl];
            float val = fmaxf(acc + accb + rt, 0.f) * m;
            if (lane < XL_) pacc += val * wdv;   // count each channel once
        }
    }

    // block-reduce pool partial
    #pragma unroll
    for (int off = 16; off > 0; off >>= 1)
        pacc += __shfl_down_sync(0xffffffffu, pacc, off);
    if (lane == 0) s.red[warp] = pacc;
    __syncthreads();
    if (warp == 0) {
        float v = s.red[lane];
        #pragma unroll
        for (int off = 16; off > 0; off >>= 1)
            v += __shfl_down_sync(0xffffffffu, v, off);
        if (lane == 0) {
            g_part[b*G_ + g] = v;
            __threadfence();
            unsigned t = atomicInc(&g_cnt[b], G_ - 1u);   // wraps to 0 each call
            if (t == G_ - 1u) {
                volatile float* p = g_part + b*G_;
                float sum = bd[0];
                #pragma unroll
                for (int k = 0; k < G_; k++) sum += p[k];
                out[b] = sum;
            }
        }
    }
}

// ---------------------------------------------------------------------------
extern "C" void kernel_launch(void* const* d_in, const int* in_sizes, int n_in,
                              void* d_out, int out_size)
{
    const float* x       = (const float*)d_in[0];
    const float* a       = (const float*)d_in[1];
    const float* e       = (const float*)d_in[2];
    const float* w1_kern = (const float*)d_in[3];
    const float* b1_kern = (const float*)d_in[4];
    const float* w1_root = (const float*)d_in[5];
    const float* b1      = (const float*)d_in[6];
    const float* w2_kern = (const float*)d_in[7];
    const float* b2_kern = (const float*)d_in[8];
    const float* w2_root = (const float*)d_in[9];
    const float* b2      = (const float*)d_in[10];
    const float* w_dense = (const float*)d_in[11];
    const float* b_dense = (const float*)d_in[12];
    float* out = (float*)d_out;

    cudaFuncSetAttribute(fused_gnn_kernel,
                         cudaFuncAttributeMaxDynamicSharedMemorySize,
                         (int)sizeof(Smem));

    fused_gnn_kernel<<<B_*G_, 1024, sizeof(Smem)>>>(
        x, a, e,
        w1_kern, b1_kern, w1_root, b1,
        w2_kern, b2_kern, w2_root, b2,
        w_dense, b_dense, out);
}